// round 5
// baseline (speedup 1.0000x reference)
#include <cuda_runtime.h>
#include <cstdint>

// EuclideanDistance: mat_1 [8192,128] f32, mat_2 [8192,128] f32 -> out [8192,8192] f32
// D[i,j] = ||a_i||^2 + ||b_j||^2 - 2 * (A B^T)[i,j]
// GEMM core: mma.sync.m16n8k8 TF32. Warp tile 64x64 (1.0 smem-wavefront/MMA),
// CTA tile 128x256, K double-buffered in 64-wide chunks via cp.async.

#define NR 8192
#define DK 128
#define NTHREADS 256

__device__ float g_sq1[NR];
__device__ float g_sq2[NR];
__device__ float g_A32[NR * DK];   // tf32-rounded copies (cvt.rna)
__device__ float g_B32[NR * DK];

// ---------------- smem layout ----------------
// A: 128 rows x 528B (132 f32, odd 16B count -> conflict-free ldmatrix)
// B: 2 stages x 256 rows x 272B (68 f32, 64 used)
#define AROWB 528
#define BROWB 272
#define SMA 0
#define SMB 67584
#define BSTAGE 69632
#define SM_TOTAL 206848

__device__ __forceinline__ uint32_t smem_u32(const void* p) {
    uint32_t a;
    asm("{ .reg .u64 t; cvta.to.shared.u64 t, %1; cvt.u32.u64 %0, t; }" : "=r"(a) : "l"(p));
    return a;
}

__device__ __forceinline__ void cpa16(uint32_t saddr, const void* gaddr) {
    asm volatile("cp.async.cg.shared.global [%0], [%1], 16;" :: "r"(saddr), "l"(gaddr));
}
__device__ __forceinline__ void cpa_commit() {
    asm volatile("cp.async.commit_group;" ::: "memory");
}

#define LDSM_X4(r0, r1, r2, r3, addr) \
    asm volatile("ldmatrix.sync.aligned.m8n8.x4.shared.b16 {%0,%1,%2,%3}, [%4];" \
                 : "=r"(r0), "=r"(r1), "=r"(r2), "=r"(r3) : "r"(addr))

#define MMA_TF32(c, a0, a1, a2, a3, b0, b1) \
    asm volatile("mma.sync.aligned.m16n8k8.row.col.f32.tf32.tf32.f32 " \
                 "{%0,%1,%2,%3}, {%4,%5,%6,%7}, {%8,%9}, {%0,%1,%2,%3};" \
                 : "+f"((c)[0]), "+f"((c)[1]), "+f"((c)[2]), "+f"((c)[3]) \
                 : "r"(a0), "r"(a1), "r"(a2), "r"(a3), "r"(b0), "r"(b1))

// A strip: 128 rows x 128 f32 (32 x 16B segs per row)
__device__ __forceinline__ void load_a(const float* __restrict__ src, uint32_t sb, int tid) {
#pragma unroll
    for (int l = 0; l < 16; l++) {
        int idx = tid + NTHREADS * l;
        int row = idx >> 5;
        int seg = idx & 31;
        cpa16(sb + SMA + row * AROWB + seg * 16, src + (size_t)row * DK + seg * 4);
    }
}

// B chunk: 256 rows x 64 f32 (16 x 16B segs per row), k-chunk kc of tile tt
__device__ __forceinline__ void load_bchunk(const float* __restrict__ B32, int tt, int kc,
                                            uint32_t stage, int tid) {
    const float* src = B32 + (size_t)tt * 256 * DK + kc * 64;
#pragma unroll
    for (int l = 0; l < 16; l++) {
        int idx = tid + NTHREADS * l;
        int row = idx >> 4;
        int seg = idx & 15;
        cpa16(stage + row * BROWB + seg * 16, src + (size_t)row * DK + seg * 4);
    }
}

__global__ void __launch_bounds__(NTHREADS, 1)
euclid_mma_kernel(const float* __restrict__ A32, const float* __restrict__ B32,
                  const float* __restrict__ sq1g, const float* __restrict__ sq2g,
                  float* __restrict__ C) {
    extern __shared__ char smem[];
    const uint32_t sb = smem_u32(smem);
    const int tid = threadIdx.x;
    const int lane = tid & 31;
    const int wid = tid >> 5;
    const int wm = wid & 1;       // 2 warp rows x 64
    const int wn = wid >> 1;      // 4 warp cols x 64
    const int m0 = blockIdx.y * 128;
    const int nt0 = blockIdx.x * 2;   // 2 N-tiles (256 wide) per CTA

    // Prologue: A strip + both K-chunks of B tile 0 (3 commit groups)
    load_a(A32 + (size_t)m0 * DK, sb, tid);
    cpa_commit();
    load_bchunk(B32, nt0, 0, sb + SMB, tid);
    cpa_commit();
    load_bchunk(B32, nt0, 1, sb + SMB + BSTAGE, tid);
    cpa_commit();

    // sq1 for this thread's output rows (fixed for whole CTA)
    float s1r[4][2];
#pragma unroll
    for (int mf = 0; mf < 4; mf++) {
        int m = m0 + wm * 64 + mf * 16 + (lane >> 2);
        s1r[mf][0] = sq1g[m];
        s1r[mf][1] = sq1g[m + 8];
    }

    // ldmatrix addresses
    uint32_t aAddr[4];
#pragma unroll
    for (int mf = 0; mf < 4; mf++) {
        int r = wm * 64 + mf * 16 + (lane & 15);
        aAddr[mf] = sb + SMA + r * AROWB + ((lane >> 4) << 4);
    }
    // B x4: two n8 fragments per load. groups: rows +0..7 (k-lo, k-hi), rows +8..15 (k-lo, k-hi)
    uint32_t bOff[4];
#pragma unroll
    for (int p = 0; p < 4; p++) {
        int r = wn * 64 + p * 16 + ((lane >> 4) & 1) * 8 + (lane & 7);
        bOff[p] = r * BROWB + (((lane >> 3) & 1) << 4);
    }

#pragma unroll 1
    for (int t = 0; t < 2; t++) {
        float acc[4][8][4];
#pragma unroll
        for (int mf = 0; mf < 4; mf++)
#pragma unroll
            for (int nf = 0; nf < 8; nf++)
#pragma unroll
                for (int q = 0; q < 4; q++) acc[mf][nf][q] = 0.0f;

#pragma unroll
        for (int kc = 0; kc < 2; kc++) {
            const int g = t * 2 + kc;           // global chunk index 0..3
            if (g < 3) {
                asm volatile("cp.async.wait_group 1;" ::: "memory");
            } else {
                asm volatile("cp.async.wait_group 0;" ::: "memory");
            }
            __syncthreads();

            const uint32_t stage = sb + SMB + (uint32_t)(g & 1) * BSTAGE;
#pragma unroll
            for (int ks = 0; ks < 8; ks++) {
                uint32_t a[4][4], bf[8][2];
#pragma unroll
                for (int mf = 0; mf < 4; mf++)
                    LDSM_X4(a[mf][0], a[mf][1], a[mf][2], a[mf][3],
                            aAddr[mf] + kc * 256 + ks * 32);
#pragma unroll
                for (int p = 0; p < 4; p++)
                    LDSM_X4(bf[p * 2][0], bf[p * 2][1], bf[p * 2 + 1][0], bf[p * 2 + 1][1],
                            stage + bOff[p] + ks * 32);
#pragma unroll
                for (int mf = 0; mf < 4; mf++)
#pragma unroll
                    for (int nf = 0; nf < 8; nf++)
                        MMA_TF32(acc[mf][nf], a[mf][0], a[mf][1], a[mf][2], a[mf][3],
                                 bf[nf][0], bf[nf][1]);
            }
            __syncthreads();  // all warps done reading stage (g&1)

            // Prefetch chunk g+2 into the stage just freed; overlaps next MMA/epilogue
            if (g + 2 < 4) {
                load_bchunk(B32, nt0 + ((g + 2) >> 1), (g + 2) & 1,
                            sb + SMB + (uint32_t)(g & 1) * BSTAGE, tid);
                cpa_commit();
            }
        }

        // Epilogue tile t: D = sq1 + sq2 - 2*dot
        const int nb = (nt0 + t) * 256 + wn * 64;
        float s2r[8][2];
#pragma unroll
        for (int nf = 0; nf < 8; nf++) {
            int n = nb + nf * 8 + 2 * (lane & 3);
            s2r[nf][0] = sq2g[n];
            s2r[nf][1] = sq2g[n + 1];
        }
#pragma unroll
        for (int mf = 0; mf < 4; mf++) {
            size_t m = (size_t)(m0 + wm * 64 + mf * 16 + (lane >> 2));
#pragma unroll
            for (int nf = 0; nf < 8; nf++) {
                int n = nb + nf * 8 + 2 * (lane & 3);
                float2 o0, o1;
                o0.x = fmaf(acc[mf][nf][0], -2.0f, s1r[mf][0] + s2r[nf][0]);
                o0.y = fmaf(acc[mf][nf][1], -2.0f, s1r[mf][0] + s2r[nf][1]);
                o1.x = fmaf(acc[mf][nf][2], -2.0f, s1r[mf][1] + s2r[nf][0]);
                o1.y = fmaf(acc[mf][nf][3], -2.0f, s1r[mf][1] + s2r[nf][1]);
                *reinterpret_cast<float2*>(C + m * NR + n) = o0;
                *reinterpret_cast<float2*>(C + (m + 8) * NR + n) = o1;
            }
        }
    }
}

// Prep: row norms (exact f32, matching reference) + tf32-rounded copies (cvt.rna).
__global__ void prep_kernel(const float* __restrict__ A, const float* __restrict__ B,
                            float* __restrict__ A32, float* __restrict__ B32,
                            float* __restrict__ sq1, float* __restrict__ sq2) {
    int w = (blockIdx.x * blockDim.x + threadIdx.x) >> 5;
    int lane = threadIdx.x & 31;
    const float* src;
    float* dst;
    float* nrm;
    int row;
    if (w < NR) {
        src = A; dst = A32; nrm = sq1; row = w;
    } else {
        src = B; dst = B32; nrm = sq2; row = w - NR;
    }
    float4 v = reinterpret_cast<const float4*>(src + (size_t)row * DK)[lane];
    float s = v.x * v.x + v.y * v.y + v.z * v.z + v.w * v.w;
#pragma unroll
    for (int o = 16; o > 0; o >>= 1) s += __shfl_xor_sync(0xffffffffu, s, o);
    if (lane == 0) nrm[row] = s;

    uint4 t;
    asm("cvt.rna.tf32.f32 %0, %1;" : "=r"(t.x) : "f"(v.x));
    asm("cvt.rna.tf32.f32 %0, %1;" : "=r"(t.y) : "f"(v.y));
    asm("cvt.rna.tf32.f32 %0, %1;" : "=r"(t.z) : "f"(v.z));
    asm("cvt.rna.tf32.f32 %0, %1;" : "=r"(t.w) : "f"(v.w));
    reinterpret_cast<uint4*>(dst + (size_t)row * DK)[lane] = t;
}

extern "C" void kernel_launch(void* const* d_in, const int* in_sizes, int n_in,
                              void* d_out, int out_size) {
    const float* A = (const float*)d_in[0];
    const float* B = (const float*)d_in[1];
    float* C = (float*)d_out;

    float *sq1, *sq2, *A32, *B32;
    cudaGetSymbolAddress((void**)&sq1, g_sq1);
    cudaGetSymbolAddress((void**)&sq2, g_sq2);
    cudaGetSymbolAddress((void**)&A32, g_A32);
    cudaGetSymbolAddress((void**)&B32, g_B32);

    cudaFuncSetAttribute(euclid_mma_kernel,
                         cudaFuncAttributeMaxDynamicSharedMemorySize, SM_TOTAL);

    prep_kernel<<<2 * NR / 8, 256>>>(A, B, A32, B32, sq1, sq2);

    dim3 grid(NR / 256 / 2, NR / 128);  // (16, 64) = 1024 CTAs
    euclid_mma_kernel<<<grid, NTHREADS, SM_TOTAL>>>(A32, B32, sq1, sq2, C);
}

// round 6
// speedup vs baseline: 1.4095x; 1.4095x over previous
#include <cuda_runtime.h>
#include <cuda_fp16.h>
#include <cstdint>

// EuclideanDistance: mat_1 [8192,128] f32, mat_2 [8192,128] f32 -> out [8192,8192] f32
// D[i,j] = ||a_i||^2 + ||b_j||^2 - 2 * (A B^T)[i,j]
// GEMM core: mma.sync.m16n8k16 FP16 (f32 accum). fp16 mantissa == tf32 mantissa,
// inputs are N(0,1) so no range risk; halves MMA instruction count vs tf32 k8.

#define NR 8192
#define DK 128
#define NTHREADS 256

__device__ float g_sq1[NR];
__device__ float g_sq2[NR];
__device__ __half g_A16[NR * DK];
__device__ __half g_B16[NR * DK];

// ---------------- smem layout ----------------
// A: 128 rows x 272B (128 fp16 = 256B + 16B pad; 17x16B odd -> conflict-free ldmatrix)
// B: 2 stages x 256 rows x 144B (64 fp16 = 128B + 16B pad)
#define AROWB 272
#define BROWB 144
#define SMA 0
#define SMB 34816
#define BSTAGE 36864
#define SM_TOTAL 108544

__device__ __forceinline__ uint32_t smem_u32(const void* p) {
    uint32_t a;
    asm("{ .reg .u64 t; cvta.to.shared.u64 t, %1; cvt.u32.u64 %0, t; }" : "=r"(a) : "l"(p));
    return a;
}

__device__ __forceinline__ void cpa16(uint32_t saddr, const void* gaddr) {
    asm volatile("cp.async.cg.shared.global [%0], [%1], 16;" :: "r"(saddr), "l"(gaddr));
}
__device__ __forceinline__ void cpa_commit() {
    asm volatile("cp.async.commit_group;" ::: "memory");
}

#define LDSM_X4(r0, r1, r2, r3, addr) \
    asm volatile("ldmatrix.sync.aligned.m8n8.x4.shared.b16 {%0,%1,%2,%3}, [%4];" \
                 : "=r"(r0), "=r"(r1), "=r"(r2), "=r"(r3) : "r"(addr))

#define MMA_F16(c, a0, a1, a2, a3, b0, b1) \
    asm volatile("mma.sync.aligned.m16n8k16.row.col.f32.f16.f16.f32 " \
                 "{%0,%1,%2,%3}, {%4,%5,%6,%7}, {%8,%9}, {%0,%1,%2,%3};" \
                 : "+f"((c)[0]), "+f"((c)[1]), "+f"((c)[2]), "+f"((c)[3]) \
                 : "r"(a0), "r"(a1), "r"(a2), "r"(a3), "r"(b0), "r"(b1))

// A strip: 128 rows x 128 fp16 (16 x 16B segs per row)
__device__ __forceinline__ void load_a(const __half* __restrict__ src, uint32_t sb, int tid) {
#pragma unroll
    for (int l = 0; l < 8; l++) {
        int idx = tid + NTHREADS * l;   // 0..2047
        int row = idx >> 4;             // 0..127
        int seg = idx & 15;
        cpa16(sb + SMA + row * AROWB + seg * 16, src + (size_t)row * DK + seg * 8);
    }
}

// B chunk: 256 rows x 64 fp16 (8 x 16B segs per row), k-chunk kc of tile tt
__device__ __forceinline__ void load_bchunk(const __half* __restrict__ B16, int tt, int kc,
                                            uint32_t stage, int tid) {
    const __half* src = B16 + (size_t)tt * 256 * DK + kc * 64;
#pragma unroll
    for (int l = 0; l < 8; l++) {
        int idx = tid + NTHREADS * l;   // 0..2047
        int row = idx >> 3;             // 0..255
        int seg = idx & 7;
        cpa16(stage + row * BROWB + seg * 16, src + (size_t)row * DK + seg * 8);
    }
}

__global__ void __launch_bounds__(NTHREADS, 1)
euclid_mma_kernel(const __half* __restrict__ A16, const __half* __restrict__ B16,
                  const float* __restrict__ sq1g, const float* __restrict__ sq2g,
                  float* __restrict__ C) {
    extern __shared__ char smem[];
    const uint32_t sb = smem_u32(smem);
    const int tid = threadIdx.x;
    const int lane = tid & 31;
    const int wid = tid >> 5;
    const int wm = wid & 1;       // 2 warp rows x 64
    const int wn = wid >> 1;      // 4 warp cols x 64
    const int m0 = blockIdx.y * 128;
    const int nt0 = blockIdx.x * 2;   // 2 N-tiles (256 wide) per CTA

    // Prologue: A strip + both K-chunks of B tile 0 (3 commit groups)
    load_a(A16 + (size_t)m0 * DK, sb, tid);
    cpa_commit();
    load_bchunk(B16, nt0, 0, sb + SMB, tid);
    cpa_commit();
    load_bchunk(B16, nt0, 1, sb + SMB + BSTAGE, tid);
    cpa_commit();

    // sq1 for this thread's output rows (fixed for whole CTA)
    float s1r[4][2];
#pragma unroll
    for (int mf = 0; mf < 4; mf++) {
        int m = m0 + wm * 64 + mf * 16 + (lane >> 2);
        s1r[mf][0] = sq1g[m];
        s1r[mf][1] = sq1g[m + 8];
    }

    // ldmatrix addresses.
    // A (m16 x k16 per step): lanes 0-15 -> rows m0..15 @ k-lo 16B, lanes 16-31 -> same rows @ k-hi.
    uint32_t aAddr[4];
#pragma unroll
    for (int mf = 0; mf < 4; mf++) {
        int r = wm * 64 + mf * 16 + (lane & 15);
        aAddr[mf] = sb + SMA + r * AROWB + ((lane >> 4) << 4);
    }
    // B x4: two n8 fragments x (k-lo, k-hi): lanes 0-7 n-rows+0..7 k-lo, 8-15 k-hi,
    // 16-23 n-rows+8..15 k-lo, 24-31 k-hi.
    uint32_t bOff[4];
#pragma unroll
    for (int p = 0; p < 4; p++) {
        int r = wn * 64 + p * 16 + ((lane >> 4) & 1) * 8 + (lane & 7);
        bOff[p] = r * BROWB + (((lane >> 3) & 1) << 4);
    }

#pragma unroll 1
    for (int t = 0; t < 2; t++) {
        float acc[4][8][4];
#pragma unroll
        for (int mf = 0; mf < 4; mf++)
#pragma unroll
            for (int nf = 0; nf < 8; nf++)
#pragma unroll
                for (int q = 0; q < 4; q++) acc[mf][nf][q] = 0.0f;

#pragma unroll
        for (int kc = 0; kc < 2; kc++) {
            const int g = t * 2 + kc;           // global chunk index 0..3
            if (g < 3) {
                asm volatile("cp.async.wait_group 1;" ::: "memory");
            } else {
                asm volatile("cp.async.wait_group 0;" ::: "memory");
            }
            __syncthreads();

            const uint32_t stage = sb + SMB + (uint32_t)(g & 1) * BSTAGE;
            // 64-wide K chunk = 4 k16-steps
#pragma unroll
            for (int ks = 0; ks < 4; ks++) {
                uint32_t a[4][4], bf[8][2];
#pragma unroll
                for (int mf = 0; mf < 4; mf++)
                    LDSM_X4(a[mf][0], a[mf][1], a[mf][2], a[mf][3],
                            aAddr[mf] + kc * 128 + ks * 32);
#pragma unroll
                for (int p = 0; p < 4; p++)
                    LDSM_X4(bf[p * 2][0], bf[p * 2][1], bf[p * 2 + 1][0], bf[p * 2 + 1][1],
                            stage + bOff[p] + ks * 32);
#pragma unroll
                for (int mf = 0; mf < 4; mf++)
#pragma unroll
                    for (int nf = 0; nf < 8; nf++)
                        MMA_F16(acc[mf][nf], a[mf][0], a[mf][1], a[mf][2], a[mf][3],
                                bf[nf][0], bf[nf][1]);
            }
            __syncthreads();  // all warps done reading stage (g&1)

            // Prefetch chunk g+2 into the stage just freed; overlaps next MMA/epilogue
            if (g + 2 < 4) {
                load_bchunk(B16, nt0 + ((g + 2) >> 1), (g + 2) & 1,
                            sb + SMB + (uint32_t)(g & 1) * BSTAGE, tid);
                cpa_commit();
            }
        }

        // Epilogue tile t: D = sq1 + sq2 - 2*dot
        const int nb = (nt0 + t) * 256 + wn * 64;
        float s2r[8][2];
#pragma unroll
        for (int nf = 0; nf < 8; nf++) {
            int n = nb + nf * 8 + 2 * (lane & 3);
            s2r[nf][0] = sq2g[n];
            s2r[nf][1] = sq2g[n + 1];
        }
#pragma unroll
        for (int mf = 0; mf < 4; mf++) {
            size_t m = (size_t)(m0 + wm * 64 + mf * 16 + (lane >> 2));
#pragma unroll
            for (int nf = 0; nf < 8; nf++) {
                int n = nb + nf * 8 + 2 * (lane & 3);
                float2 o0, o1;
                o0.x = fmaf(acc[mf][nf][0], -2.0f, s1r[mf][0] + s2r[nf][0]);
                o0.y = fmaf(acc[mf][nf][1], -2.0f, s1r[mf][0] + s2r[nf][1]);
                o1.x = fmaf(acc[mf][nf][2], -2.0f, s1r[mf][1] + s2r[nf][0]);
                o1.y = fmaf(acc[mf][nf][3], -2.0f, s1r[mf][1] + s2r[nf][1]);
                *reinterpret_cast<float2*>(C + m * NR + n) = o0;
                *reinterpret_cast<float2*>(C + (m + 8) * NR + n) = o1;
            }
        }
    }
}

// Prep: row norms (exact f32, matching reference) + fp16 copies.
__global__ void prep_kernel(const float* __restrict__ A, const float* __restrict__ B,
                            __half* __restrict__ A16, __half* __restrict__ B16,
                            float* __restrict__ sq1, float* __restrict__ sq2) {
    int w = (blockIdx.x * blockDim.x + threadIdx.x) >> 5;
    int lane = threadIdx.x & 31;
    const float* src;
    __half* dst;
    float* nrm;
    int row;
    if (w < NR) {
        src = A; dst = A16; nrm = sq1; row = w;
    } else {
        src = B; dst = B16; nrm = sq2; row = w - NR;
    }
    float4 v = reinterpret_cast<const float4*>(src + (size_t)row * DK)[lane];
    float s = v.x * v.x + v.y * v.y + v.z * v.z + v.w * v.w;
#pragma unroll
    for (int o = 16; o > 0; o >>= 1) s += __shfl_xor_sync(0xffffffffu, s, o);
    if (lane == 0) nrm[row] = s;

    __half2 h01 = __floats2half2_rn(v.x, v.y);
    __half2 h23 = __floats2half2_rn(v.z, v.w);
    uint2 packed;
    packed.x = *reinterpret_cast<uint32_t*>(&h01);
    packed.y = *reinterpret_cast<uint32_t*>(&h23);
    *reinterpret_cast<uint2*>(dst + (size_t)row * DK + lane * 4) = packed;
}

extern "C" void kernel_launch(void* const* d_in, const int* in_sizes, int n_in,
                              void* d_out, int out_size) {
    const float* A = (const float*)d_in[0];
    const float* B = (const float*)d_in[1];
    float* C = (float*)d_out;

    float *sq1, *sq2;
    __half *A16, *B16;
    cudaGetSymbolAddress((void**)&sq1, g_sq1);
    cudaGetSymbolAddress((void**)&sq2, g_sq2);
    cudaGetSymbolAddress((void**)&A16, g_A16);
    cudaGetSymbolAddress((void**)&B16, g_B16);

    cudaFuncSetAttribute(euclid_mma_kernel,
                         cudaFuncAttributeMaxDynamicSharedMemorySize, SM_TOTAL);

    prep_kernel<<<2 * NR / 8, 256>>>(A, B, A16, B16, sq1, sq2);

    dim3 grid(NR / 256 / 2, NR / 128);  // (16, 64) = 1024 CTAs
    euclid_mma_kernel<<<grid, NTHREADS, SM_TOTAL>>>(A16, B16, sq1, sq2, C);
}

// round 7
// speedup vs baseline: 1.6792x; 1.1913x over previous
#include <cuda_runtime.h>
#include <cuda_fp16.h>
#include <cstdint>

// EuclideanDistance: mat_1 [8192,128] f32, mat_2 [8192,128] f32 -> out [8192,8192] f32
// D[i,j] = ||a_i||^2 + ||b_j||^2 - 2 * (A B^T)[i,j]
// GEMM: mma.sync.m16n8k16 FP16 (f32 accum), warp tile 64x64, CTA tile 128x128,
// 128-thread CTAs at 2 CTAs/SM so one CTA's sync/epilogue gaps are covered by
// the other's MMA stream (R6 was latency-bound at 1 CTA/SM: issue 12.9%).

#define NR 8192
#define DK 128
#define NTH 128

__device__ float g_sq1[NR];
__device__ float g_sq2[NR];
__device__ __half g_A16[NR * DK];
__device__ __half g_B16[NR * DK];

// ---------------- smem layout ----------------
// A: 128 rows x 272B (128 fp16 + 16B pad; 17x16B odd -> conflict-free ldmatrix)
// B: 2 stages x 128 rows x 144B (64 fp16 + 16B pad)
#define AROWB 272
#define BROWB 144
#define SMA 0
#define SMB 34816
#define BSTAGE 18432
#define SM_TOTAL 71680

__device__ __forceinline__ uint32_t smem_u32(const void* p) {
    uint32_t a;
    asm("{ .reg .u64 t; cvta.to.shared.u64 t, %1; cvt.u32.u64 %0, t; }" : "=r"(a) : "l"(p));
    return a;
}

__device__ __forceinline__ void cpa16(uint32_t saddr, const void* gaddr) {
    asm volatile("cp.async.cg.shared.global [%0], [%1], 16;" :: "r"(saddr), "l"(gaddr));
}
__device__ __forceinline__ void cpa_commit() {
    asm volatile("cp.async.commit_group;" ::: "memory");
}

#define LDSM_X4(r0, r1, r2, r3, addr) \
    asm volatile("ldmatrix.sync.aligned.m8n8.x4.shared.b16 {%0,%1,%2,%3}, [%4];" \
                 : "=r"(r0), "=r"(r1), "=r"(r2), "=r"(r3) : "r"(addr))

#define MMA_F16(c, a0, a1, a2, a3, b0, b1) \
    asm volatile("mma.sync.aligned.m16n8k16.row.col.f32.f16.f16.f32 " \
                 "{%0,%1,%2,%3}, {%4,%5,%6,%7}, {%8,%9}, {%0,%1,%2,%3};" \
                 : "+f"((c)[0]), "+f"((c)[1]), "+f"((c)[2]), "+f"((c)[3]) \
                 : "r"(a0), "r"(a1), "r"(a2), "r"(a3), "r"(b0), "r"(b1))

// A strip: 128 rows x 128 fp16 (16 x 16B segs per row), 2048 segs / 128 thr
__device__ __forceinline__ void load_a(const __half* __restrict__ src, uint32_t sb, int tid) {
#pragma unroll
    for (int l = 0; l < 16; l++) {
        int idx = tid + NTH * l;
        int row = idx >> 4;
        int seg = idx & 15;
        cpa16(sb + SMA + row * AROWB + seg * 16, src + (size_t)row * DK + seg * 8);
    }
}

// B chunk: 128 rows x 64 fp16 (8 x 16B segs per row), k-chunk kc of N-tile tt
__device__ __forceinline__ void load_bchunk(const __half* __restrict__ B16, int tt, int kc,
                                            uint32_t stage, int tid) {
    const __half* src = B16 + (size_t)tt * 128 * DK + kc * 64;
#pragma unroll
    for (int l = 0; l < 8; l++) {
        int idx = tid + NTH * l;
        int row = idx >> 3;
        int seg = idx & 7;
        cpa16(stage + row * BROWB + seg * 16, src + (size_t)row * DK + seg * 8);
    }
}

__global__ void __launch_bounds__(NTH, 2)
euclid_mma_kernel(const __half* __restrict__ A16, const __half* __restrict__ B16,
                  const float* __restrict__ sq1g, const float* __restrict__ sq2g,
                  float* __restrict__ C) {
    extern __shared__ char smem[];
    const uint32_t sb = smem_u32(smem);
    const int tid = threadIdx.x;
    const int lane = tid & 31;
    const int wid = tid >> 5;
    const int wm = wid & 1;            // 2 warp rows x 64
    const int wn = (wid >> 1) & 1;     // 2 warp cols x 64
    const int m0 = blockIdx.y * 128;
    const int nt0 = blockIdx.x * 2;    // 2 N-tiles (128 wide each) per CTA

    // Prologue: A strip + both K-chunks of B tile 0 (3 commit groups)
    load_a(A16 + (size_t)m0 * DK, sb, tid);
    cpa_commit();
    load_bchunk(B16, nt0, 0, sb + SMB, tid);
    cpa_commit();
    load_bchunk(B16, nt0, 1, sb + SMB + BSTAGE, tid);
    cpa_commit();

    // sq1 for this thread's output rows (fixed for whole CTA)
    float s1r[4][2];
#pragma unroll
    for (int mf = 0; mf < 4; mf++) {
        int m = m0 + wm * 64 + mf * 16 + (lane >> 2);
        s1r[mf][0] = sq1g[m];
        s1r[mf][1] = sq1g[m + 8];
    }

    // ldmatrix addresses.
    // A (m16 x k16 per step): lanes 0-15 rows @ k-lo 16B, lanes 16-31 same rows @ k-hi.
    uint32_t aAddr[4];
#pragma unroll
    for (int mf = 0; mf < 4; mf++) {
        int r = wm * 64 + mf * 16 + (lane & 15);
        aAddr[mf] = sb + SMA + r * AROWB + ((lane >> 4) << 4);
    }
    // B x4: two n8 fragments x (k-lo, k-hi)
    uint32_t bOff[4];
#pragma unroll
    for (int p = 0; p < 4; p++) {
        int r = wn * 64 + p * 16 + ((lane >> 4) & 1) * 8 + (lane & 7);
        bOff[p] = r * BROWB + (((lane >> 3) & 1) << 4);
    }

#pragma unroll 1
    for (int t = 0; t < 2; t++) {
        float acc[4][8][4];
#pragma unroll
        for (int mf = 0; mf < 4; mf++)
#pragma unroll
            for (int nf = 0; nf < 8; nf++)
#pragma unroll
                for (int q = 0; q < 4; q++) acc[mf][nf][q] = 0.0f;

#pragma unroll
        for (int kc = 0; kc < 2; kc++) {
            const int g = t * 2 + kc;           // global chunk index 0..3
            if (g < 3) {
                asm volatile("cp.async.wait_group 1;" ::: "memory");
            } else {
                asm volatile("cp.async.wait_group 0;" ::: "memory");
            }
            __syncthreads();

            const uint32_t stage = sb + SMB + (uint32_t)(g & 1) * BSTAGE;
            // 64-wide K chunk = 4 k16-steps
#pragma unroll
            for (int ks = 0; ks < 4; ks++) {
                uint32_t a[4][4], bf[8][2];
#pragma unroll
                for (int mf = 0; mf < 4; mf++)
                    LDSM_X4(a[mf][0], a[mf][1], a[mf][2], a[mf][3],
                            aAddr[mf] + kc * 128 + ks * 32);
#pragma unroll
                for (int p = 0; p < 4; p++)
                    LDSM_X4(bf[p * 2][0], bf[p * 2][1], bf[p * 2 + 1][0], bf[p * 2 + 1][1],
                            stage + bOff[p] + ks * 32);
#pragma unroll
                for (int mf = 0; mf < 4; mf++)
#pragma unroll
                    for (int nf = 0; nf < 8; nf++)
                        MMA_F16(acc[mf][nf], a[mf][0], a[mf][1], a[mf][2], a[mf][3],
                                bf[nf][0], bf[nf][1]);
            }
            __syncthreads();  // all warps done reading stage (g&1)

            // Prefetch chunk g+2 into the stage just freed
            if (g + 2 < 4) {
                load_bchunk(B16, nt0 + ((g + 2) >> 1), (g + 2) & 1,
                            sb + SMB + (uint32_t)(g & 1) * BSTAGE, tid);
                cpa_commit();
            }
        }

        // Epilogue tile t: D = sq1 + sq2 - 2*dot
        const int nb = (nt0 + t) * 128 + wn * 64;
        float s2r[8][2];
#pragma unroll
        for (int nf = 0; nf < 8; nf++) {
            int n = nb + nf * 8 + 2 * (lane & 3);
            s2r[nf][0] = sq2g[n];
            s2r[nf][1] = sq2g[n + 1];
        }
#pragma unroll
        for (int mf = 0; mf < 4; mf++) {
            size_t m = (size_t)(m0 + wm * 64 + mf * 16 + (lane >> 2));
#pragma unroll
            for (int nf = 0; nf < 8; nf++) {
                int n = nb + nf * 8 + 2 * (lane & 3);
                float2 o0, o1;
                o0.x = fmaf(acc[mf][nf][0], -2.0f, s1r[mf][0] + s2r[nf][0]);
                o0.y = fmaf(acc[mf][nf][1], -2.0f, s1r[mf][0] + s2r[nf][1]);
                o1.x = fmaf(acc[mf][nf][2], -2.0f, s1r[mf][1] + s2r[nf][0]);
                o1.y = fmaf(acc[mf][nf][3], -2.0f, s1r[mf][1] + s2r[nf][1]);
                *reinterpret_cast<float2*>(C + m * NR + n) = o0;
                *reinterpret_cast<float2*>(C + (m + 8) * NR + n) = o1;
            }
        }
    }
}

// Prep: row norms (exact f32, matching reference) + fp16 copies.
__global__ void prep_kernel(const float* __restrict__ A, const float* __restrict__ B,
                            __half* __restrict__ A16, __half* __restrict__ B16,
                            float* __restrict__ sq1, float* __restrict__ sq2) {
    int w = (blockIdx.x * blockDim.x + threadIdx.x) >> 5;
    int lane = threadIdx.x & 31;
    const float* src;
    __half* dst;
    float* nrm;
    int row;
    if (w < NR) {
        src = A; dst = A16; nrm = sq1; row = w;
    } else {
        src = B; dst = B16; nrm = sq2; row = w - NR;
    }
    float4 v = reinterpret_cast<const float4*>(src + (size_t)row * DK)[lane];
    float s = v.x * v.x + v.y * v.y + v.z * v.z + v.w * v.w;
#pragma unroll
    for (int o = 16; o > 0; o >>= 1) s += __shfl_xor_sync(0xffffffffu, s, o);
    if (lane == 0) nrm[row] = s;

    __half2 h01 = __floats2half2_rn(v.x, v.y);
    __half2 h23 = __floats2half2_rn(v.z, v.w);
    uint2 packed;
    packed.x = *reinterpret_cast<uint32_t*>(&h01);
    packed.y = *reinterpret_cast<uint32_t*>(&h23);
    *reinterpret_cast<uint2*>(dst + (size_t)row * DK + lane * 4) = packed;
}

extern "C" void kernel_launch(void* const* d_in, const int* in_sizes, int n_in,
                              void* d_out, int out_size) {
    const float* A = (const float*)d_in[0];
    const float* B = (const float*)d_in[1];
    float* C = (float*)d_out;

    float *sq1, *sq2;
    __half *A16, *B16;
    cudaGetSymbolAddress((void**)&sq1, g_sq1);
    cudaGetSymbolAddress((void**)&sq2, g_sq2);
    cudaGetSymbolAddress((void**)&A16, g_A16);
    cudaGetSymbolAddress((void**)&B16, g_B16);

    cudaFuncSetAttribute(euclid_mma_kernel,
                         cudaFuncAttributeMaxDynamicSharedMemorySize, SM_TOTAL);

    prep_kernel<<<2 * NR / 8, 256>>>(A, B, A16, B16, sq1, sq2);

    dim3 grid(NR / 128 / 2, NR / 128);  // (32, 64) = 2048 CTAs, 2/SM
    euclid_mma_kernel<<<grid, NTH, SM_TOTAL>>>(A16, B16, sq1, sq2, C);
}

// round 8
// speedup vs baseline: 1.7623x; 1.0495x over previous
#include <cuda_runtime.h>
#include <cuda_fp16.h>
#include <cstdint>

// EuclideanDistance: mat_1 [8192,128] f32, mat_2 [8192,128] f32 -> out [8192,8192] f32
// D[i,j] = ||a_i||^2 + ||b_j||^2 - 2 * (A B^T)[i,j]
// GEMM: mma.sync.m16n8k16 FP16 (f32 accum), warp 64x64, CTA 128x128, 2 CTAs/SM.
// R8: whole B working set (4 chunks) prefetched in prologue into 4 smem stages,
// consumed via decreasing cp.async.wait_group -> one barrier per chunk, zero
// buffer reuse; C written with st.global.cs (write-once data, skip L2 retention).

#define NR 8192
#define DK 128
#define NTH 128

__device__ float g_sq1[NR];
__device__ float g_sq2[NR];
__device__ __half g_A16[NR * DK];
__device__ __half g_B16[NR * DK];

// ---------------- smem layout ----------------
// A: 128 rows x 272B (128 fp16 + 16B pad; 17x16B odd -> conflict-free ldmatrix)
// B: 4 stages x 128 rows x 144B (64 fp16 + 16B pad)
#define AROWB 272
#define BROWB 144
#define SMA 0
#define SMB 34816
#define BSTAGE 18432
#define SM_TOTAL (34816 + 4 * 18432)   // 108544

__device__ __forceinline__ uint32_t smem_u32(const void* p) {
    uint32_t a;
    asm("{ .reg .u64 t; cvta.to.shared.u64 t, %1; cvt.u32.u64 %0, t; }" : "=r"(a) : "l"(p));
    return a;
}

__device__ __forceinline__ void cpa16(uint32_t saddr, const void* gaddr) {
    asm volatile("cp.async.cg.shared.global [%0], [%1], 16;" :: "r"(saddr), "l"(gaddr));
}
__device__ __forceinline__ void cpa_commit() {
    asm volatile("cp.async.commit_group;" ::: "memory");
}

#define LDSM_X4(r0, r1, r2, r3, addr) \
    asm volatile("ldmatrix.sync.aligned.m8n8.x4.shared.b16 {%0,%1,%2,%3}, [%4];" \
                 : "=r"(r0), "=r"(r1), "=r"(r2), "=r"(r3) : "r"(addr))

#define MMA_F16(c, a0, a1, a2, a3, b0, b1) \
    asm volatile("mma.sync.aligned.m16n8k16.row.col.f32.f16.f16.f32 " \
                 "{%0,%1,%2,%3}, {%4,%5,%6,%7}, {%8,%9}, {%0,%1,%2,%3};" \
                 : "+f"((c)[0]), "+f"((c)[1]), "+f"((c)[2]), "+f"((c)[3]) \
                 : "r"(a0), "r"(a1), "r"(a2), "r"(a3), "r"(b0), "r"(b1))

// A strip: 128 rows x 128 fp16 (16 x 16B segs per row), 2048 segs / 128 thr
__device__ __forceinline__ void load_a(const __half* __restrict__ src, uint32_t sb, int tid) {
#pragma unroll
    for (int l = 0; l < 16; l++) {
        int idx = tid + NTH * l;
        int row = idx >> 4;
        int seg = idx & 15;
        cpa16(sb + SMA + row * AROWB + seg * 16, src + (size_t)row * DK + seg * 8);
    }
}

// B chunk: 128 rows x 64 fp16 (8 x 16B segs per row), k-chunk kc of N-tile tt
__device__ __forceinline__ void load_bchunk(const __half* __restrict__ B16, int tt, int kc,
                                            uint32_t stage, int tid) {
    const __half* src = B16 + (size_t)tt * 128 * DK + kc * 64;
#pragma unroll
    for (int l = 0; l < 8; l++) {
        int idx = tid + NTH * l;
        int row = idx >> 3;
        int seg = idx & 7;
        cpa16(stage + row * BROWB + seg * 16, src + (size_t)row * DK + seg * 8);
    }
}

__global__ void __launch_bounds__(NTH, 2)
euclid_mma_kernel(const __half* __restrict__ A16, const __half* __restrict__ B16,
                  const float* __restrict__ sq1g, const float* __restrict__ sq2g,
                  float* __restrict__ C) {
    extern __shared__ char smem[];
    const uint32_t sb = smem_u32(smem);
    const int tid = threadIdx.x;
    const int lane = tid & 31;
    const int wid = tid >> 5;
    const int wm = wid & 1;            // 2 warp rows x 64
    const int wn = (wid >> 1) & 1;     // 2 warp cols x 64
    const int m0 = blockIdx.y * 128;
    const int nt0 = blockIdx.x * 2;    // 2 N-tiles (128 wide each) per CTA

    // Prologue: A + chunk0 (group0), chunk1..3 (groups 1..3). All B resident;
    // no stage is ever rewritten -> single barrier per chunk, no reuse hazards.
    load_a(A16 + (size_t)m0 * DK, sb, tid);
    load_bchunk(B16, nt0, 0, sb + SMB + 0 * BSTAGE, tid);
    cpa_commit();
    load_bchunk(B16, nt0, 1, sb + SMB + 1 * BSTAGE, tid);
    cpa_commit();
    load_bchunk(B16, nt0 + 1, 0, sb + SMB + 2 * BSTAGE, tid);
    cpa_commit();
    load_bchunk(B16, nt0 + 1, 1, sb + SMB + 3 * BSTAGE, tid);
    cpa_commit();

    // sq1 for this thread's output rows (fixed for whole CTA)
    float s1r[4][2];
#pragma unroll
    for (int mf = 0; mf < 4; mf++) {
        int m = m0 + wm * 64 + mf * 16 + (lane >> 2);
        s1r[mf][0] = sq1g[m];
        s1r[mf][1] = sq1g[m + 8];
    }

    // ldmatrix addresses.
    uint32_t aAddr[4];
#pragma unroll
    for (int mf = 0; mf < 4; mf++) {
        int r = wm * 64 + mf * 16 + (lane & 15);
        aAddr[mf] = sb + SMA + r * AROWB + ((lane >> 4) << 4);
    }
    uint32_t bOff[4];
#pragma unroll
    for (int p = 0; p < 4; p++) {
        int r = wn * 64 + p * 16 + ((lane >> 4) & 1) * 8 + (lane & 7);
        bOff[p] = r * BROWB + (((lane >> 3) & 1) << 4);
    }

#pragma unroll
    for (int t = 0; t < 2; t++) {
        float acc[4][8][4];
#pragma unroll
        for (int mf = 0; mf < 4; mf++)
#pragma unroll
            for (int nf = 0; nf < 8; nf++)
#pragma unroll
                for (int q = 0; q < 4; q++) acc[mf][nf][q] = 0.0f;

#pragma unroll
        for (int kc = 0; kc < 2; kc++) {
            const int g = t * 2 + kc;           // chunk/stage index 0..3
            if (g == 0)      asm volatile("cp.async.wait_group 3;" ::: "memory");
            else if (g == 1) asm volatile("cp.async.wait_group 2;" ::: "memory");
            else if (g == 2) asm volatile("cp.async.wait_group 1;" ::: "memory");
            else             asm volatile("cp.async.wait_group 0;" ::: "memory");
            __syncthreads();

            const uint32_t stage = sb + SMB + (uint32_t)g * BSTAGE;
            // 64-wide K chunk = 4 k16-steps
#pragma unroll
            for (int ks = 0; ks < 4; ks++) {
                uint32_t a[4][4], bf[8][2];
#pragma unroll
                for (int mf = 0; mf < 4; mf++)
                    LDSM_X4(a[mf][0], a[mf][1], a[mf][2], a[mf][3],
                            aAddr[mf] + kc * 128 + ks * 32);
#pragma unroll
                for (int p = 0; p < 4; p++)
                    LDSM_X4(bf[p * 2][0], bf[p * 2][1], bf[p * 2 + 1][0], bf[p * 2 + 1][1],
                            stage + bOff[p] + ks * 32);
#pragma unroll
                for (int mf = 0; mf < 4; mf++)
#pragma unroll
                    for (int nf = 0; nf < 8; nf++)
                        MMA_F16(acc[mf][nf], a[mf][0], a[mf][1], a[mf][2], a[mf][3],
                                bf[nf][0], bf[nf][1]);
            }
        }

        // Epilogue tile t: D = sq1 + sq2 - 2*dot; streaming stores (write-once)
        const int nb = (nt0 + t) * 128 + wn * 64;
        float s2r[8][2];
#pragma unroll
        for (int nf = 0; nf < 8; nf++) {
            int n = nb + nf * 8 + 2 * (lane & 3);
            s2r[nf][0] = sq2g[n];
            s2r[nf][1] = sq2g[n + 1];
        }
#pragma unroll
        for (int mf = 0; mf < 4; mf++) {
            size_t m = (size_t)(m0 + wm * 64 + mf * 16 + (lane >> 2));
#pragma unroll
            for (int nf = 0; nf < 8; nf++) {
                int n = nb + nf * 8 + 2 * (lane & 3);
                float2 o0, o1;
                o0.x = fmaf(acc[mf][nf][0], -2.0f, s1r[mf][0] + s2r[nf][0]);
                o0.y = fmaf(acc[mf][nf][1], -2.0f, s1r[mf][0] + s2r[nf][1]);
                o1.x = fmaf(acc[mf][nf][2], -2.0f, s1r[mf][1] + s2r[nf][0]);
                o1.y = fmaf(acc[mf][nf][3], -2.0f, s1r[mf][1] + s2r[nf][1]);
                __stcs(reinterpret_cast<float2*>(C + m * NR + n), o0);
                __stcs(reinterpret_cast<float2*>(C + (m + 8) * NR + n), o1);
            }
        }
    }
}

// Prep: row norms (exact f32, matching reference) + fp16 copies.
__global__ void prep_kernel(const float* __restrict__ A, const float* __restrict__ B,
                            __half* __restrict__ A16, __half* __restrict__ B16,
                            float* __restrict__ sq1, float* __restrict__ sq2) {
    int w = (blockIdx.x * blockDim.x + threadIdx.x) >> 5;
    int lane = threadIdx.x & 31;
    const float* src;
    __half* dst;
    float* nrm;
    int row;
    if (w < NR) {
        src = A; dst = A16; nrm = sq1; row = w;
    } else {
        src = B; dst = B16; nrm = sq2; row = w - NR;
    }
    float4 v = reinterpret_cast<const float4*>(src + (size_t)row * DK)[lane];
    float s = v.x * v.x + v.y * v.y + v.z * v.z + v.w * v.w;
#pragma unroll
    for (int o = 16; o > 0; o >>= 1) s += __shfl_xor_sync(0xffffffffu, s, o);
    if (lane == 0) nrm[row] = s;

    __half2 h01 = __floats2half2_rn(v.x, v.y);
    __half2 h23 = __floats2half2_rn(v.z, v.w);
    uint2 packed;
    packed.x = *reinterpret_cast<uint32_t*>(&h01);
    packed.y = *reinterpret_cast<uint32_t*>(&h23);
    *reinterpret_cast<uint2*>(dst + (size_t)row * DK + lane * 4) = packed;
}

extern "C" void kernel_launch(void* const* d_in, const int* in_sizes, int n_in,
                              void* d_out, int out_size) {
    const float* A = (const float*)d_in[0];
    const float* B = (const float*)d_in[1];
    float* C = (float*)d_out;

    float *sq1, *sq2;
    __half *A16, *B16;
    cudaGetSymbolAddress((void**)&sq1, g_sq1);
    cudaGetSymbolAddress((void**)&sq2, g_sq2);
    cudaGetSymbolAddress((void**)&A16, g_A16);
    cudaGetSymbolAddress((void**)&B16, g_B16);

    cudaFuncSetAttribute(euclid_mma_kernel,
                         cudaFuncAttributeMaxDynamicSharedMemorySize, SM_TOTAL);

    prep_kernel<<<2 * NR / 8, 256>>>(A, B, A16, B16, sq1, sq2);

    dim3 grid(NR / 128 / 2, NR / 128);  // (32, 64) = 2048 CTAs, 2/SM
    euclid_mma_kernel<<<grid, NTH, SM_TOTAL>>>(A16, B16, sq1, sq2, C);
}